// round 4
// baseline (speedup 1.0000x reference)
#include <cuda_runtime.h>
#include <cstdint>

// Problem constants (fixed shapes):
//   B=128, T=2048, F_IN=32, R=256, H=256, F_OUT=32, future_n=64
//   total tokens N = 128 * (2048+64) = 270336
#define NTOTAL 270336
#define TTOT   2112
#define TIN    2048

// Fused weights:  M = W_ih @ enc_W  ->  gates[n] = x[n] @ M^T + fused_bias
// f-gate dropped (c0 == 0). Layout [k][hj] (k-major) for vectorized smem fill.
__device__ float g_Mi[32 * 256];
__device__ float g_Mg[32 * 256];
__device__ float g_Mo[32 * 256];
__device__ float g_bi[256];
__device__ float g_bg[256];
__device__ float g_bo[256];
// h scratch: [NTOTAL][256] fp32 (276.8 MB, static device array per harness rules)
__device__ float g_h[(size_t)NTOTAL * 256];

// ---- packed f32x2 helpers (sm_103a; ptxas won't auto-fuse, PTX only) ----
typedef unsigned long long u64t;
__device__ __forceinline__ void ffma2(u64t& d, u64t a, u64t b) {
    asm("fma.rn.f32x2 %0, %1, %2, %0;" : "+l"(d) : "l"(a), "l"(b));
}
__device__ __forceinline__ u64t pack2(float x, float y) {
    u64t r; asm("mov.b64 %0, {%1,%2};" : "=l"(r) : "f"(x), "f"(y)); return r;
}
__device__ __forceinline__ void unpack2(float& lo, float& hi, u64t v) {
    asm("mov.b64 {%0,%1}, %2;" : "=f"(lo), "=f"(hi) : "l"(v));
}
// MUFU.TANH (sm_75+) based activations: 1 MUFU each
__device__ __forceinline__ float tanh_a(float v) {
    float r; asm("tanh.approx.f32 %0, %1;" : "=f"(r) : "f"(v)); return r;
}
__device__ __forceinline__ float sig_a(float v) {
    return fmaf(0.5f, tanh_a(0.5f * v), 0.5f);
}

// ---------------------------------------------------------------------------
// K1: fold encoder into LSTM input weights. Warp-per-output, shfl reduce.
//   25344 outputs (24576 M + 768 bias) -> 3168 blocks x 8 warps.
// ---------------------------------------------------------------------------
__global__ void prep_kernel(const float* __restrict__ Wih,
                            const float* __restrict__ encW,
                            const float* __restrict__ encb,
                            const float* __restrict__ bih,
                            const float* __restrict__ bhh) {
    int gw   = (blockIdx.x * blockDim.x + threadIdx.x) >> 5;
    int lane = threadIdx.x & 31;
    if (gw < 24576) {                        // 3 planes * 256 hj * 32 k
        int p   = gw >> 13;
        int rem = gw & 8191;
        int hj  = rem >> 5;
        int k   = rem & 31;
        int row = hj + (p == 0 ? 0 : (p == 1 ? 512 : 768));
        const float* wr = Wih + row * 256;
        float s = 0.0f;
        #pragma unroll
        for (int r = lane; r < 256; r += 32) s += wr[r] * encW[r * 32 + k];
        #pragma unroll
        for (int off = 16; off; off >>= 1) s += __shfl_xor_sync(0xffffffffu, s, off);
        if (lane == 0) {
            float* dst = (p == 0) ? g_Mi : (p == 1 ? g_Mg : g_Mo);
            dst[k * 256 + hj] = s;
        }
    } else if (gw < 25344) {
        int q  = gw - 24576;
        int p  = q >> 8;
        int hj = q & 255;
        int row = hj + (p == 0 ? 0 : (p == 1 ? 512 : 768));
        const float* wr = Wih + row * 256;
        float s = 0.0f;
        #pragma unroll
        for (int r = lane; r < 256; r += 32) s += wr[r] * encb[r];
        #pragma unroll
        for (int off = 16; off; off >>= 1) s += __shfl_xor_sync(0xffffffffu, s, off);
        if (lane == 0) {
            float* dst = (p == 0) ? g_bi : (p == 1 ? g_bg : g_bo);
            dst[hj] = s + bih[row] + bhh[row];
        }
    }
}

// ---------------------------------------------------------------------------
// K2: gates GEMM (K=32, f32x2-packed) + LSTM elementwise -> g_h.
// Grid: (4 hj-slices of 64, 2112 token-tiles). Block = 256 threads.
// Block tile: 128 tok x 64 hj; thread tile: 8 tok x 4 hj x 3 gates
// (48 packed f32x2 accumulators). M-operand LDS amortized over 8 tokens so
// per-SM LDS cycles stay under per-SMSP FMA cycles.
// ---------------------------------------------------------------------------
__global__ __launch_bounds__(256, 1)
void gates_kernel(const float* __restrict__ x) {
    __shared__ __align__(16) float Mi_s[32 * 64];
    __shared__ __align__(16) float Mg_s[32 * 64];
    __shared__ __align__(16) float Mo_s[32 * 64];
    __shared__ float bi_s[64], bg_s[64], bo_s[64];
    __shared__ __align__(16) float X_s[128 * 36];   // [tok][32], pad 36

    int tid   = threadIdx.x;
    int hbase = blockIdx.x * 64;

    for (int i = tid; i < 2048; i += 256) {
        int k = i >> 6, j = i & 63;
        Mi_s[i] = g_Mi[k * 256 + hbase + j];
        Mg_s[i] = g_Mg[k * 256 + hbase + j];
        Mo_s[i] = g_Mo[k * 256 + hbase + j];
    }
    if (tid < 64) {
        bi_s[tid] = g_bi[hbase + tid];
        bg_s[tid] = g_bg[hbase + tid];
        bo_s[tid] = g_bo[hbase + tid];
    }

    int n0 = blockIdx.y * 128;
    {   // load X tile [128 tok][32] (t >= 2048 clamps to last input step)
        #pragma unroll
        for (int w = 0; w < 4; w++) {
            int idx = tid + w * 256;             // 1024 float4s
            int tk = idx >> 3, seg = idx & 7;
            int n = n0 + tk;
            int b = n / TTOT;
            int t = n - b * TTOT;
            if (t > TIN - 1) t = TIN - 1;
            *(float4*)&X_s[tk * 36 + seg * 4] =
                *(const float4*)(x + (size_t)(b * TIN + t) * 32 + seg * 4);
        }
    }
    __syncthreads();

    int hj0  = (tid & 15) * 4;
    int tok0 = (tid >> 4) * 8;

    u64t ai[8][2], ag[8][2], ao[8][2];
    #pragma unroll
    for (int j = 0; j < 8; j++) {
        ai[j][0] = 0; ai[j][1] = 0;
        ag[j][0] = 0; ag[j][1] = 0;
        ao[j][0] = 0; ao[j][1] = 0;
    }

    #pragma unroll
    for (int k4 = 0; k4 < 32; k4 += 4) {
        float4 xv[8];
        #pragma unroll
        for (int j = 0; j < 8; j++)
            xv[j] = *(const float4*)&X_s[(tok0 + j) * 36 + k4];
        #pragma unroll
        for (int kk = 0; kk < 4; kk++) {
            ulonglong2 mi = *(const ulonglong2*)&Mi_s[(k4 + kk) * 64 + hj0];
            ulonglong2 mg = *(const ulonglong2*)&Mg_s[(k4 + kk) * 64 + hj0];
            ulonglong2 mo = *(const ulonglong2*)&Mo_s[(k4 + kk) * 64 + hj0];
            #pragma unroll
            for (int j = 0; j < 8; j++) {
                float xs = ((const float*)&xv[j])[kk];
                u64t xx = pack2(xs, xs);
                ffma2(ai[j][0], xx, mi.x); ffma2(ai[j][1], xx, mi.y);
                ffma2(ag[j][0], xx, mg.x); ffma2(ag[j][1], xx, mg.y);
                ffma2(ao[j][0], xx, mo.x); ffma2(ao[j][1], xx, mo.y);
            }
        }
    }

    // LSTM elementwise (c0=0): h = sig(o) * tanh(sig(i) * tanh(g))
    #pragma unroll
    for (int j = 0; j < 8; j++) {
        size_t n = (size_t)(n0 + tok0 + j);
        float4 hv;
        float* hp = (float*)&hv;
        #pragma unroll
        for (int pr = 0; pr < 2; pr++) {
            float i0, i1, g0, g1, o0, o1;
            unpack2(i0, i1, ai[j][pr]);
            unpack2(g0, g1, ag[j][pr]);
            unpack2(o0, o1, ao[j][pr]);
            int q = pr * 2;
            i0 += bi_s[hj0 + q];     i1 += bi_s[hj0 + q + 1];
            g0 += bg_s[hj0 + q];     g1 += bg_s[hj0 + q + 1];
            o0 += bo_s[hj0 + q];     o1 += bo_s[hj0 + q + 1];
            float c0v = sig_a(i0) * tanh_a(g0);
            float c1v = sig_a(i1) * tanh_a(g1);
            hp[q]     = sig_a(o0) * tanh_a(c0v);
            hp[q + 1] = sig_a(o1) * tanh_a(c1v);
        }
        *(float4*)&g_h[n * 256 + hbase + hj0] = hv;
    }
}

// ---------------------------------------------------------------------------
// K3: decoder GEMM  out[n][o] = sum_k dec_W[o][k] * h[n][k] + dec_b[o]
// Block tile: 256 tokens x 32 outs; thread tile: 8 tok x 2 o-pairs packed
// along K (f32x2, horizontal add at the end). k chunked by 32 through smem.
// ---------------------------------------------------------------------------
__global__ __launch_bounds__(256, 2)
void dec_kernel(const float* __restrict__ decW,
                const float* __restrict__ decb,
                float* __restrict__ out) {
    __shared__ __align__(16) float w_s[32 * 260];   // [o][256] pad 260
    __shared__ __align__(16) float h_s[256 * 36];   // [tok][32] pad 36
    int tid = threadIdx.x;

    for (int i = tid; i < 8192; i += 256) {
        int o = i >> 8, k = i & 255;
        w_s[o * 260 + k] = decW[i];
    }
    int og = tid & 7, tokg = tid >> 3;
    int o0 = og * 4, tok0 = tokg * 8;
    int n0 = blockIdx.x * 256;

    u64t acc[8][4];
    #pragma unroll
    for (int m = 0; m < 8; m++)
        #pragma unroll
        for (int i = 0; i < 4; i++) acc[m][i] = 0;

    for (int c = 0; c < 8; c++) {
        __syncthreads();
        #pragma unroll
        for (int w = 0; w < 8; w++) {            // 256 tok x 32 k = 2048 f4
            int idx = tid + w * 256;
            int tok = idx >> 3, seg = idx & 7;
            *(float4*)&h_s[tok * 36 + seg * 4] =
                *(const float4*)&g_h[(size_t)(n0 + tok) * 256 + c * 32 + seg * 4];
        }
        __syncthreads();
        const float* wb = &w_s[o0 * 260 + c * 32];
        #pragma unroll
        for (int k4 = 0; k4 < 32; k4 += 4) {
            ulonglong2 w0 = *(const ulonglong2*)(wb + k4);
            ulonglong2 w1 = *(const ulonglong2*)(wb + 260 + k4);
            ulonglong2 w2 = *(const ulonglong2*)(wb + 520 + k4);
            ulonglong2 w3 = *(const ulonglong2*)(wb + 780 + k4);
            #pragma unroll
            for (int m = 0; m < 8; m++) {
                ulonglong2 hv = *(const ulonglong2*)&h_s[(tok0 + m) * 36 + k4];
                ffma2(acc[m][0], hv.x, w0.x); ffma2(acc[m][0], hv.y, w0.y);
                ffma2(acc[m][1], hv.x, w1.x); ffma2(acc[m][1], hv.y, w1.y);
                ffma2(acc[m][2], hv.x, w2.x); ffma2(acc[m][2], hv.y, w2.y);
                ffma2(acc[m][3], hv.x, w3.x); ffma2(acc[m][3], hv.y, w3.y);
            }
        }
    }
    float db0 = decb[o0], db1 = decb[o0 + 1], db2 = decb[o0 + 2], db3 = decb[o0 + 3];
    #pragma unroll
    for (int m = 0; m < 8; m++) {
        float4 r;
        float lo, hi;
        unpack2(lo, hi, acc[m][0]); r.x = lo + hi + db0;
        unpack2(lo, hi, acc[m][1]); r.y = lo + hi + db1;
        unpack2(lo, hi, acc[m][2]); r.z = lo + hi + db2;
        unpack2(lo, hi, acc[m][3]); r.w = lo + hi + db3;
        *(float4*)&out[(size_t)(n0 + tok0 + m) * 32 + o0] = r;
    }
}

// ---------------------------------------------------------------------------
// Inputs (metadata order): input_seq, enc_W, enc_b, W_ih, W_hh, b_ih, b_hh,
//                          dec_W, dec_b, future_n
// W_hh is dead (state never updates from zeros); future_n fixed at 64.
// ---------------------------------------------------------------------------
extern "C" void kernel_launch(void* const* d_in, const int* in_sizes, int n_in,
                              void* d_out, int out_size) {
    (void)in_sizes; (void)n_in; (void)out_size;
    const float* input = (const float*)d_in[0];
    const float* encW  = (const float*)d_in[1];
    const float* encb  = (const float*)d_in[2];
    const float* Wih   = (const float*)d_in[3];
    const float* bih   = (const float*)d_in[5];
    const float* bhh   = (const float*)d_in[6];
    const float* decW  = (const float*)d_in[7];
    const float* decb  = (const float*)d_in[8];
    float* out = (float*)d_out;

    prep_kernel<<<3168, 256>>>(Wih, encW, encb, bih, bhh);
    dim3 g2(4, NTOTAL / 128);               // 4 hj-slices x 2112 token-tiles
    gates_kernel<<<g2, 256>>>(input);
    dec_kernel<<<NTOTAL / 256, 256>>>(decW, decb, out);
}

// round 5
// speedup vs baseline: 1.3361x; 1.3361x over previous
#include <cuda_runtime.h>
#include <cstdint>

// Problem constants (fixed shapes):
//   B=128, T=2048, F_IN=32, R=256, H=256, F_OUT=32, future_n=64
//   total tokens N = 128 * (2048+64) = 270336
#define NTOTAL 270336
#define TTOT   2112
#define TIN    2048
#define NTILES (NTOTAL / 64)   // 4224

// Fused weights:  M = W_ih @ enc_W  ->  gates[n] = x[n] @ M^T + fused_bias
// f-gate dropped (c0 == 0). Layout [k][hj] (k-major).
__device__ float g_Mi[32 * 256];
__device__ float g_Mg[32 * 256];
__device__ float g_Mo[32 * 256];
__device__ float g_bi[256];
__device__ float g_bg[256];
__device__ float g_bo[256];

// ---- packed f32x2 helpers (sm_103a; PTX-only, ptxas won't auto-fuse) ----
typedef unsigned long long u64t;
__device__ __forceinline__ void ffma2(u64t& d, u64t a, u64t b) {
    asm("fma.rn.f32x2 %0, %1, %2, %0;" : "+l"(d) : "l"(a), "l"(b));
}
__device__ __forceinline__ u64t pack2(float x, float y) {
    u64t r; asm("mov.b64 %0, {%1,%2};" : "=l"(r) : "f"(x), "f"(y)); return r;
}
__device__ __forceinline__ void unpack2(float& lo, float& hi, u64t v) {
    asm("mov.b64 {%0,%1}, %2;" : "=f"(lo), "=f"(hi) : "l"(v));
}
// MUFU.TANH-based activations (validated rel_err ~5e-6 in R4)
__device__ __forceinline__ float tanh_a(float v) {
    float r; asm("tanh.approx.f32 %0, %1;" : "=f"(r) : "f"(v)); return r;
}
__device__ __forceinline__ float sig_a(float v) {
    return fmaf(0.5f, tanh_a(0.5f * v), 0.5f);
}

// ---------------------------------------------------------------------------
// K1: fold encoder into LSTM input weights. One 32-thread block per M row
// (W_ih row staged in smem, each thread owns one k; encW reads coalesced).
// Blocks 768..791 compute the 768 fused biases (one output per lane).
// ---------------------------------------------------------------------------
__global__ void prep_kernel(const float* __restrict__ Wih,
                            const float* __restrict__ encW,
                            const float* __restrict__ encb,
                            const float* __restrict__ bih,
                            const float* __restrict__ bhh) {
    __shared__ float wr_s[256];
    int bid = blockIdx.x, lane = threadIdx.x;
    if (bid < 768) {                       // M rows: 3 planes * 256 hj
        int p  = bid >> 8;
        int hj = bid & 255;
        int row = hj + (p == 0 ? 0 : (p == 1 ? 512 : 768));
        const float* wr = Wih + row * 256;
        #pragma unroll
        for (int i = 0; i < 8; i++) wr_s[lane + 32 * i] = wr[lane + 32 * i];
        __syncwarp();
        int k = lane;
        float s = 0.0f;
        #pragma unroll 8
        for (int r = 0; r < 256; r++) s += wr_s[r] * encW[r * 32 + k];
        float* dst = (p == 0) ? g_Mi : (p == 1 ? g_Mg : g_Mo);
        dst[k * 256 + hj] = s;
    } else {                               // biases: 24 blocks * 32 lanes = 768
        int q = (bid - 768) * 32 + lane;   // 0..767
        int p  = q >> 8;
        int hj = q & 255;
        int row = hj + (p == 0 ? 0 : (p == 1 ? 512 : 768));
        const float* wr = Wih + row * 256;
        float s = 0.0f;
        #pragma unroll 8
        for (int r = 0; r < 256; r++) s += wr[r] * encb[r];
        float* dst = (p == 0) ? g_bi : (p == 1 ? g_bg : g_bo);
        dst[hj] = s + bih[row] + bhh[row];
    }
}

// ---------------------------------------------------------------------------
// K_init: out[n][o] = dec_b[o]   (REDG partials accumulate on top)
// ---------------------------------------------------------------------------
__global__ void init_out_kernel(const float* __restrict__ decb,
                                float* __restrict__ out) {
    int idx = blockIdx.x * blockDim.x + threadIdx.x;   // float4 index
    float4 v = *(const float4*)&decb[(idx & 7) * 4];
    ((float4*)out)[idx] = v;
}

// ---------------------------------------------------------------------------
// K2: fused gates GEMM (K=32) + LSTM elementwise + partial decoder.
// Grid: (4 hj-slices of 64, 74 strips). Block = 256 threads, occ 2.
// Gates: thread tile 4 tok x 4 hj x 3 gates (f32x2-packed along hj).
// Then h-tile [64x64] -> smem, partial decode out += h @ dec_W_sliceT
// (thread tile 2 tok x 4 o, full K=64, f32x2 along o) via atomicAdd (REDG).
// ---------------------------------------------------------------------------
__global__ __launch_bounds__(256, 2)
void fused_kernel(const float* __restrict__ x,
                  const float* __restrict__ decW,
                  float* __restrict__ out) {
    __shared__ __align__(16) float Mi_s[32 * 64];
    __shared__ __align__(16) float Mg_s[32 * 64];
    __shared__ __align__(16) float Mo_s[32 * 64];
    __shared__ float bi_s[64], bg_s[64], bo_s[64];
    __shared__ __align__(16) float X_s[64 * 36];    // [tok][32], pad 36
    __shared__ __align__(16) float h_s[64 * 68];    // [tok][64], pad 68
    __shared__ __align__(16) float w_s[64 * 36];    // [k(=hj)][32 o], pad 36

    int tid   = threadIdx.x;
    int hbase = blockIdx.x * 64;

    for (int i = tid; i < 2048; i += 256) {
        int k = i >> 6, j = i & 63;
        Mi_s[i] = g_Mi[k * 256 + hbase + j];
        Mg_s[i] = g_Mg[k * 256 + hbase + j];
        Mo_s[i] = g_Mo[k * 256 + hbase + j];
    }
    if (tid < 64) {
        bi_s[tid] = g_bi[hbase + tid];
        bg_s[tid] = g_bg[hbase + tid];
        bo_s[tid] = g_bo[hbase + tid];
    }
    // decoder slice: w_s[k][o] = decW[o][hbase + k]   (transposed store)
    for (int i = tid; i < 2048; i += 256) {
        int o = i & 31, k = i >> 5;
        w_s[k * 36 + o] = decW[o * 256 + hbase + k];
    }

    int hjg = tid & 15, tokg = tid >> 4;
    int hj0 = hjg * 4, tok0 = tokg * 4;
    // decode mapping: 2 tok x 4 o per thread
    int d_og   = tid & 7;          // o0 = d_og*4
    int d_tokg = tid >> 3;         // 32 groups of 2 tokens
    int d_o0   = d_og * 4;
    int d_t0   = d_tokg * 2;

    for (int tile = blockIdx.y; tile < NTILES; tile += gridDim.y) {
        int n0 = tile * 64;
        __syncthreads();
        {   // load X tile [64 tok][32] (t >= 2048 clamps to last input step)
            int tk = tid >> 2, seg = tid & 3;
            int n = n0 + tk;
            int b = n / TTOT;
            int t = n - b * TTOT;
            if (t > TIN - 1) t = TIN - 1;
            const float* src = x + (size_t)(b * TIN + t) * 32 + seg * 8;
            float4 a0 = *(const float4*)src;
            float4 a1 = *(const float4*)(src + 4);
            *(float4*)&X_s[tk * 36 + seg * 8]     = a0;
            *(float4*)&X_s[tk * 36 + seg * 8 + 4] = a1;
        }
        __syncthreads();

        u64t ai[4][2], ag[4][2], ao[4][2];
        #pragma unroll
        for (int j = 0; j < 4; j++) {
            ai[j][0] = 0; ai[j][1] = 0;
            ag[j][0] = 0; ag[j][1] = 0;
            ao[j][0] = 0; ao[j][1] = 0;
        }

        #pragma unroll
        for (int k4 = 0; k4 < 32; k4 += 4) {
            float4 xv[4];
            #pragma unroll
            for (int j = 0; j < 4; j++)
                xv[j] = *(const float4*)&X_s[(tok0 + j) * 36 + k4];
            #pragma unroll
            for (int kk = 0; kk < 4; kk++) {
                ulonglong2 mi = *(const ulonglong2*)&Mi_s[(k4 + kk) * 64 + hj0];
                ulonglong2 mg = *(const ulonglong2*)&Mg_s[(k4 + kk) * 64 + hj0];
                ulonglong2 mo = *(const ulonglong2*)&Mo_s[(k4 + kk) * 64 + hj0];
                #pragma unroll
                for (int j = 0; j < 4; j++) {
                    float xs = ((const float*)&xv[j])[kk];
                    u64t xx = pack2(xs, xs);
                    ffma2(ai[j][0], xx, mi.x); ffma2(ai[j][1], xx, mi.y);
                    ffma2(ag[j][0], xx, mg.x); ffma2(ag[j][1], xx, mg.y);
                    ffma2(ao[j][0], xx, mo.x); ffma2(ao[j][1], xx, mo.y);
                }
            }
        }

        // LSTM elementwise (c0=0): h = sig(o) * tanh(sig(i) * tanh(g)) -> h_s
        #pragma unroll
        for (int j = 0; j < 4; j++) {
            float4 hv;
            float* hp = (float*)&hv;
            #pragma unroll
            for (int pr = 0; pr < 2; pr++) {
                float i0, i1, g0, g1, o0v, o1v;
                unpack2(i0, i1, ai[j][pr]);
                unpack2(g0, g1, ag[j][pr]);
                unpack2(o0v, o1v, ao[j][pr]);
                int q = pr * 2;
                i0  += bi_s[hj0 + q];   i1  += bi_s[hj0 + q + 1];
                g0  += bg_s[hj0 + q];   g1  += bg_s[hj0 + q + 1];
                o0v += bo_s[hj0 + q];   o1v += bo_s[hj0 + q + 1];
                float c0v = sig_a(i0) * tanh_a(g0);
                float c1v = sig_a(i1) * tanh_a(g1);
                hp[q]     = sig_a(o0v) * tanh_a(c0v);
                hp[q + 1] = sig_a(o1v) * tanh_a(c1v);
            }
            *(float4*)&h_s[(tok0 + j) * 68 + hj0] = hv;
        }
        __syncthreads();

        // Partial decode: out[n0+t][o] += sum_{k<64} h_s[t][k] * w_s[k][o]
        {
            u64t acc[2][2];
            acc[0][0] = 0; acc[0][1] = 0; acc[1][0] = 0; acc[1][1] = 0;
            #pragma unroll 4
            for (int k4 = 0; k4 < 64; k4 += 4) {
                float4 h0 = *(const float4*)&h_s[d_t0 * 68 + k4];
                float4 h1 = *(const float4*)&h_s[(d_t0 + 1) * 68 + k4];
                #pragma unroll
                for (int kk = 0; kk < 4; kk++) {
                    ulonglong2 wv = *(const ulonglong2*)&w_s[(k4 + kk) * 36 + d_o0];
                    float hs0 = ((const float*)&h0)[kk];
                    float hs1 = ((const float*)&h1)[kk];
                    u64t p0 = pack2(hs0, hs0);
                    u64t p1 = pack2(hs1, hs1);
                    ffma2(acc[0][0], p0, wv.x); ffma2(acc[0][1], p0, wv.y);
                    ffma2(acc[1][0], p1, wv.x); ffma2(acc[1][1], p1, wv.y);
                }
            }
            #pragma unroll
            for (int j = 0; j < 2; j++) {
                float* op = &out[(size_t)(n0 + d_t0 + j) * 32 + d_o0];
                float a, b;
                unpack2(a, b, acc[j][0]);
                atomicAdd(op,     a);
                atomicAdd(op + 1, b);
                unpack2(a, b, acc[j][1]);
                atomicAdd(op + 2, a);
                atomicAdd(op + 3, b);
            }
        }
    }
}

// ---------------------------------------------------------------------------
// Inputs (metadata order): input_seq, enc_W, enc_b, W_ih, W_hh, b_ih, b_hh,
//                          dec_W, dec_b, future_n
// W_hh is dead (state never updates from zeros); future_n fixed at 64.
// ---------------------------------------------------------------------------
extern "C" void kernel_launch(void* const* d_in, const int* in_sizes, int n_in,
                              void* d_out, int out_size) {
    (void)in_sizes; (void)n_in; (void)out_size;
    const float* input = (const float*)d_in[0];
    const float* encW  = (const float*)d_in[1];
    const float* encb  = (const float*)d_in[2];
    const float* Wih   = (const float*)d_in[3];
    const float* bih   = (const float*)d_in[5];
    const float* bhh   = (const float*)d_in[6];
    const float* decW  = (const float*)d_in[7];
    const float* decb  = (const float*)d_in[8];
    float* out = (float*)d_out;

    prep_kernel<<<792, 32>>>(Wih, encW, encb, bih, bhh);
    init_out_kernel<<<(NTOTAL * 32 / 4) / 256, 256>>>(decb, out);
    dim3 g2(4, 74);
    fused_kernel<<<g2, 256>>>(input, decW, out);
}